// round 5
// baseline (speedup 1.0000x reference)
#include <cuda_runtime.h>

#define N_NODES 20000
#define N_EDGES 200000
#define D 32
#define R 100
#define EPS 1e-5f
#define NB 400          // histogram/scatter blocks
#define EPB 500         // edges per block (NB*EPB == N_EDGES)
#define FULL 0xffffffffu

// ---------------- device scratch (static, no runtime allocation) --------
__device__ int   g_dcnt[N_NODES];           // per-dst edge counts
__device__ int   g_doff[N_NODES + 1];       // CSR offsets by dst
__device__ int   g_dcur[N_NODES];           // scatter cursors by dst
__device__ int   g_bh[R * NB];              // per-(relation, block) histogram
__device__ int   g_boff[R * NB];            // per-(relation, block) base offset
__device__ int   g_hist[R];                 // per-relation totals
__device__ int   g_off[R + 1];              // exclusive scan of g_hist
__device__ int   g_chunkbase[R + 1];        // exclusive scan of chunk counts
__device__ int   g_ssrc[N_EDGES];           // src sorted by etype
__device__ int   g_dpos[N_EDGES];           // dst-order slot per etype-sorted edge
__device__ float g_msg[N_EDGES * D];        // messages, stored in DST order
__device__ float g_sum[D], g_sumsq[D];
__device__ int   g_nchunk;

// ---------------- K0: zero per-call accumulators ----------------
__global__ void k0_zero() {
    int i = blockIdx.x * blockDim.x + threadIdx.x;
    int stride = gridDim.x * blockDim.x;
    for (int j = i; j < N_NODES; j += stride) g_dcnt[j] = 0;
    if (i < D) { g_sum[i] = 0.f; g_sumsq[i] = 0.f; }
}

// ---------------- K1: per-block etype histograms + global dst histogram --
__global__ void __launch_bounds__(256) k1_hist(const int* __restrict__ etype,
                                               const int* __restrict__ dst) {
    __shared__ int sh[R];
    for (int i = threadIdx.x; i < R; i += blockDim.x) sh[i] = 0;
    __syncthreads();
    int base = blockIdx.x * EPB;
    for (int i = threadIdx.x; i < EPB; i += blockDim.x) {
        atomicAdd(&sh[etype[base + i]], 1);
        atomicAdd(&g_dcnt[dst[base + i]], 1);   // 20K spread addrs: cheap
    }
    __syncthreads();
    for (int r = threadIdx.x; r < R; r += blockDim.x)
        g_bh[r * NB + blockIdx.x] = sh[r];
}

// ---------------- K2: ALL scans, register-batched, one 1024-thread block --
__global__ void __launch_bounds__(1024) k2_scan() {
    __shared__ int wsum[32], wbase[32];
    const int lane = threadIdx.x & 31;
    const int wid  = threadIdx.x >> 5;
    const int tid  = threadIdx.x;

    // ===== phase A: dst-count exclusive scan (register-batched) =====
    {
        const int NPT = 20;                       // 1024*20 >= 20000
        int base_i = tid * NPT;
        int v[NPT];
        int lsum = 0;
#pragma unroll
        for (int j = 0; j < NPT; j++) {
            int i = base_i + j;
            v[j] = (i < N_NODES) ? g_dcnt[i] : 0; // batched loads, MLP=20
            lsum += v[j];
        }
        int s = lsum;
#pragma unroll
        for (int d = 1; d < 32; d <<= 1) {
            int t = __shfl_up_sync(FULL, s, d);
            if (lane >= d) s += t;
        }
        int excl = s - lsum;
        if (lane == 31) wsum[wid] = s;
        __syncthreads();
        if (wid == 0) {
            int v2 = wsum[lane], s2 = v2;
#pragma unroll
            for (int d = 1; d < 32; d <<= 1) {
                int t = __shfl_up_sync(FULL, s2, d);
                if (lane >= d) s2 += t;
            }
            wbase[lane] = s2 - v2;
            if (lane == 31) g_doff[N_NODES] = s2;
        }
        __syncthreads();
        int run = wbase[wid] + excl;
#pragma unroll
        for (int j = 0; j < NPT; j++) {
            int i = base_i + j;
            if (i < N_NODES) { g_doff[i] = run; g_dcur[i] = run; run += v[j]; }
        }
    }
    __syncthreads();

    // ===== phase B: per-relation local scans over blocks (warp/relation) ==
    for (int r = wid; r < R; r += 32) {
        const int CPL = (NB + 31) / 32;           // 13
        int v[CPL], pre[CPL], tot[CPL];
#pragma unroll
        for (int j = 0; j < CPL; j++) {
            int b = j * 32 + lane;
            v[j] = (b < NB) ? g_bh[r * NB + b] : 0;
        }
#pragma unroll
        for (int j = 0; j < CPL; j++) {           // independent scans (ILP)
            int s = v[j];
#pragma unroll
            for (int d = 1; d < 32; d <<= 1) {
                int t = __shfl_up_sync(FULL, s, d);
                if (lane >= d) s += t;
            }
            pre[j] = s - v[j];
            tot[j] = __shfl_sync(FULL, s, 31);
        }
        int base = 0;
#pragma unroll
        for (int j = 0; j < CPL; j++) {
            int b = j * 32 + lane;
            if (b < NB) g_boff[r * NB + b] = base + pre[j];  // local (no g_off yet)
            base += tot[j];
        }
        if (lane == 0) g_hist[r] = base;
    }
    __syncthreads();

    // ===== phase C: scan relation totals + chunk counts (warp 0) =====
    if (wid == 0) {
        int acc = 0, cacc = 0;
        for (int b0 = 0; b0 < R; b0 += 32) {
            int r = b0 + lane;
            int hv = (r < R) ? g_hist[r] : 0;
            int cv = (hv + 31) >> 5;
            int hs = hv, cs = cv;
#pragma unroll
            for (int d = 1; d < 32; d <<= 1) {
                int t1 = __shfl_up_sync(FULL, hs, d);
                int t2 = __shfl_up_sync(FULL, cs, d);
                if (lane >= d) { hs += t1; cs += t2; }
            }
            if (r < R) {
                g_off[r] = acc + hs - hv;
                g_chunkbase[r] = cacc + cs - cv;
            }
            acc  += __shfl_sync(FULL, hs, 31);
            cacc += __shfl_sync(FULL, cs, 31);
        }
        if (lane == 0) { g_off[R] = acc; g_chunkbase[R] = cacc; g_nchunk = cacc; }
    }
    __syncthreads();

    // ===== phase D: add relation bases to boff (fully parallel) =====
    for (int idx = tid; idx < R * NB; idx += 1024)
        g_boff[idx] += g_off[idx / NB];
}

// ---------------- K3: dual scatter (etype perm + dst slot) ----------------
__global__ void __launch_bounds__(256) k3_scatter(
    const int* __restrict__ etype, const int* __restrict__ src,
    const int* __restrict__ dst)
{
    __shared__ int cur[R];
    for (int r = threadIdx.x; r < R; r += blockDim.x)
        cur[r] = g_boff[r * NB + blockIdx.x];
    __syncthreads();
    int base = blockIdx.x * EPB;
    for (int i = threadIdx.x; i < EPB; i += blockDim.x) {
        int e = base + i;
        int pos = atomicAdd(&cur[etype[e]], 1);    // shared, low contention
        g_ssrc[pos] = src[e];
        g_dpos[pos] = atomicAdd(&g_dcur[dst[e]], 1);  // 20K spread addrs
    }
}

// ---------------- K4: GEMV pass — shared h-tile + packed f32x2 FMA --------
// One warp = one 32-edge chunk of one relation (binary search on chunkbase).
// Lane d holds packed column-pairs of W[r]; per edge: 8 LDS.128 + 16 FFMA2.
// Messages are stored DIRECTLY in dst-sorted order (g_dpos).
__global__ void __launch_bounds__(128) k4_compute(
    const float* __restrict__ h, const float* __restrict__ weight)
{
    __shared__ __align__(16) float tile[4][32][32];
    __shared__ int s_cb[R + 1], s_off[R + 1];
    const int lane = threadIdx.x & 31;
    const int wid  = threadIdx.x >> 5;
    const int warp = (blockIdx.x * blockDim.x + threadIdx.x) >> 5;
    const int nwarp = (gridDim.x * blockDim.x) >> 5;

    for (int i = threadIdx.x; i <= R; i += blockDim.x) {
        s_cb[i] = g_chunkbase[i];
        s_off[i] = g_off[i];
    }
    __syncthreads();
    const int nchunk = g_nchunk;

    float lsum = 0.f, lsq = 0.f;

    for (int w = warp; w < nchunk; w += nwarp) {
        int lo2 = 0, hi2 = R;                      // largest r: cb[r] <= w
        while (lo2 < hi2) {
            int mid = (lo2 + hi2 + 1) >> 1;
            if (s_cb[mid] <= w) lo2 = mid; else hi2 = mid - 1;
        }
        int r = lo2;
        int s = s_off[r] + ((w - s_cb[r]) << 5);
        int n = min(32, s_off[r + 1] - s);

        // pack W columns for this lane into 16 f32x2 registers
        const float* wp = weight + r * (D * D) + lane;
        unsigned long long wc2[16];
#pragma unroll
        for (int k = 0; k < 16; k++) {
            float w0 = wp[(2 * k) * 32];
            float w1 = wp[(2 * k + 1) * 32];
            asm("mov.b64 %0, {%1, %2};" : "=l"(wc2[k]) : "f"(w0), "f"(w1));
        }

        int sj = 0, dj = 0;
        if (lane < n) { sj = g_ssrc[s + lane]; dj = g_dpos[s + lane]; }
        for (int j = 0; j < n; j++) {
            int sje = __shfl_sync(FULL, sj, j);
            tile[wid][j][lane] = h[sje * D + lane];   // coalesced 128B
        }
        __syncwarp();

        for (int j = 0; j < n; j++) {
            const ulonglong2* row = (const ulonglong2*)tile[wid][j];
            unsigned long long a0 = 0ull, a1 = 0ull, a2 = 0ull, a3 = 0ull;
#pragma unroll
            for (int kk = 0; kk < 8; kk += 2) {
                ulonglong2 q0 = row[kk];              // LDS.128 broadcast
                ulonglong2 q1 = row[kk + 1];
                asm("fma.rn.f32x2 %0, %1, %2, %0;" : "+l"(a0) : "l"(q0.x), "l"(wc2[2 * kk + 0]));
                asm("fma.rn.f32x2 %0, %1, %2, %0;" : "+l"(a1) : "l"(q0.y), "l"(wc2[2 * kk + 1]));
                asm("fma.rn.f32x2 %0, %1, %2, %0;" : "+l"(a2) : "l"(q1.x), "l"(wc2[2 * kk + 2]));
                asm("fma.rn.f32x2 %0, %1, %2, %0;" : "+l"(a3) : "l"(q1.y), "l"(wc2[2 * kk + 3]));
            }
            float x0, x1, x2, x3, x4, x5, x6, x7;
            asm("mov.b64 {%0, %1}, %2;" : "=f"(x0), "=f"(x1) : "l"(a0));
            asm("mov.b64 {%0, %1}, %2;" : "=f"(x2), "=f"(x3) : "l"(a1));
            asm("mov.b64 {%0, %1}, %2;" : "=f"(x4), "=f"(x5) : "l"(a2));
            asm("mov.b64 {%0, %1}, %2;" : "=f"(x6), "=f"(x7) : "l"(a3));
            float acc = fmaxf(((x0 + x1) + (x2 + x3)) + ((x4 + x5) + (x6 + x7)), 0.f);
            lsum += acc;
            lsq = fmaf(acc, acc, lsq);
            int dpj = __shfl_sync(FULL, dj, j);
            g_msg[dpj * D + lane] = acc;              // full-128B-line store
        }
        __syncwarp();
    }
    __shared__ float ssum[4][32], ssq[4][32];
    ssum[wid][lane] = lsum; ssq[wid][lane] = lsq;
    __syncthreads();
    if (wid == 0) {
        float ts = ssum[0][lane] + ssum[1][lane] + ssum[2][lane] + ssum[3][lane];
        float tq = ssq[0][lane] + ssq[1][lane] + ssq[2][lane] + ssq[3][lane];
        atomicAdd(&g_sum[lane], ts);
        atomicAdd(&g_sumsq[lane], tq);
    }
}

// ---------------- K6: contiguous per-node reduce + folded BN affine ------
__global__ void __launch_bounds__(128) k6_reduce(
    float* __restrict__ out, const float* __restrict__ gamma,
    const float* __restrict__ beta)
{
    __shared__ float s_sc[32], s_sh[32];
    if (threadIdx.x < 32) {
        int d = threadIdx.x;
        float inv_e = 1.0f / (float)N_EDGES;
        float mu = g_sum[d] * inv_e;
        float var = fmaxf(g_sumsq[d] * inv_e - mu * mu, 0.f);
        float scale = rsqrtf(var + EPS) * gamma[d];
        s_sc[d] = scale;
        s_sh[d] = beta[d] - mu * scale;
    }
    __syncthreads();

    const int lane = threadIdx.x & 31;
    const int node = (blockIdx.x * blockDim.x + threadIdx.x) >> 5;
    if (node >= N_NODES) return;

    int off = g_doff[node], end = g_doff[node + 1];
    int cnt = end - off;
    float acc = 0.f;
    const float* p = g_msg + (size_t)off * D + lane;
    int i = 0;
#pragma unroll 4
    for (; i + 4 <= cnt; i += 4) {                 // contiguous rows, MLP=4
        float v0 = p[(i + 0) * D];
        float v1 = p[(i + 1) * D];
        float v2 = p[(i + 2) * D];
        float v3 = p[(i + 3) * D];
        acc += (v0 + v1) + (v2 + v3);
    }
    for (; i < cnt; i++) acc += p[i * D];

    float v = 0.f;
    if (cnt > 0) v = fmaf(acc * (1.0f / (float)cnt), s_sc[lane], s_sh[lane]);
    out[node * D + lane] = v;
}

extern "C" void kernel_launch(void* const* d_in, const int* in_sizes, int n_in,
                              void* d_out, int out_size) {
    const float* h      = (const float*)d_in[0];
    const float* weight = (const float*)d_in[1];
    const float* gamma  = (const float*)d_in[2];
    const float* beta   = (const float*)d_in[3];
    const int*   src    = (const int*)d_in[4];
    const int*   dst    = (const int*)d_in[5];
    const int*   etype  = (const int*)d_in[6];
    float* out = (float*)d_out;

    k0_zero<<<160, 128>>>();
    k1_hist<<<NB, 256>>>(etype, dst);
    k2_scan<<<1, 1024>>>();
    k3_scatter<<<NB, 256>>>(etype, src, dst);
    k4_compute<<<1600, 128>>>(h, weight);
    k6_reduce<<<(N_NODES * 32 + 127) / 128, 128>>>(out, gamma, beta);
}